// round 11
// baseline (speedup 1.0000x reference)
#include <cuda_runtime.h>
#include <math.h>

#define NSP   16384
#define NPIX  (512*512)
#define NE    262144
#define CAP   64        // max entries per segment (mean 16, 12-sigma bound)

// GEMM dynamic smem: 2 stages of As[128][36] + Bs[32][72] (unsigned words)
#define GEMM_SMEM_WORDS (2*128*36 + 2*32*72)
#define GEMM_SMEM_BYTES (GEMM_SMEM_WORDS * 4)

// ---------------------------------------------------------------------------
// Static scratch (no allocations allowed). Zero-initialized at module load;
// counters are re-zeroed by their LAST consumer each run (self-cleaning).
// ---------------------------------------------------------------------------
struct __align__(256) Scratch {
    float sp [NSP * 128];     // pooled superpixel features (tf32-rounded)
    float hb0[NSP * 128];     // layer ping (tf32-rounded)
    float hb1[NSP * 128];     // layer pong (tf32-rounded)
    float h4 [NSP * 128];     // H1+H2+H3 (tf32-rounded at final write)
    float ab [NSP * 256];     // per-node [A | B] for current layer
    float wp1[128 * 256];     // W1 folded (tf32-rounded)
    float wp2[128 * 256];     // W2 folded (tf32-rounded)
    float wfold[128 * 144];   // folded conv*linear (tf32-rounded)
    float biasf[16];          // bc@Wl + bl (full precision)
    float P  [NSP * 144];     // per-superpixel tap contributions
    int cnt_pix[NSP];         // per-sp pixel count (zeroed by k_pool)
    int cnt_e  [NSP];         // per-sp in-edge count (zeroed by last k_segmax)
    int pix_lst[NSP * CAP];   // padded CSR: pixels
    int src_lst[NSP * CAP];   // padded CSR: edge srcs
};
__device__ Scratch g_s;

// ---------------------------------------------------------------------------
// Small helpers
// ---------------------------------------------------------------------------
__device__ __forceinline__ float4 f4max(float4 a, float4 b) {
    return make_float4(fmaxf(a.x, b.x), fmaxf(a.y, b.y),
                       fmaxf(a.z, b.z), fmaxf(a.w, b.w));
}
__device__ __forceinline__ float4 f4add(float4 a, float4 b) {
    return make_float4(a.x + b.x, a.y + b.y, a.z + b.z, a.w + b.w);
}
__device__ __forceinline__ unsigned f2tf32(float f) {
    unsigned u;
    asm("cvt.rna.tf32.f32 %0, %1;" : "=r"(u) : "f"(f));
    return u;
}
__device__ __forceinline__ float rtf(float f) {
    return __uint_as_float(f2tf32(f));
}
__device__ __forceinline__ float4 r4(float4 v) {
    return make_float4(rtf(v.x), rtf(v.y), rtf(v.z), rtf(v.w));
}

// ---------------------------------------------------------------------------
// k_begin: CSR scatter (blocks 0..1023) + weight prep (blocks 1024..).
// Counters arrive pre-zeroed (module load or self-cleaning consumers).
// ---------------------------------------------------------------------------
#define PREPW (2 * 32768 + 128 * 144 + 16)
#define BEGIN_BLOCKS (1024 + (PREPW + 255) / 256)

__global__ void k_begin(const int* __restrict__ seg, int* __restrict__ cpix,
                        int* __restrict__ plst, const int* __restrict__ ei,
                        int* __restrict__ ce, int* __restrict__ elst,
                        const float* __restrict__ W1, float* __restrict__ Wp1,
                        const float* __restrict__ W2, float* __restrict__ Wp2,
                        const float* __restrict__ Wc, const float* __restrict__ Wl,
                        const float* __restrict__ bc, const float* __restrict__ bl,
                        float* __restrict__ wfold, float* __restrict__ biasf) {
    int b = blockIdx.x;
    if (b < 1024) {
        int i = b * 256 + threadIdx.x;       // i < NPIX == NE
        {
            int k = seg[i];
            int p = atomicAdd(&cpix[k], 1);
            if (p < CAP) plst[k * CAP + p] = i;
        }
        {
            int d = ei[NE + i];
            int p = atomicAdd(&ce[d], 1);
            if (p < CAP) elst[d * CAP + p] = ei[i];
        }
    } else {
        int t = (b - 1024) * 256 + threadIdx.x;
        if (t < 2 * 32768) {
            const float* W = (t < 32768) ? W1 : W2;
            float* Wp = (t < 32768) ? Wp1 : Wp2;
            int u = t & 32767;
            int j = u & 255, k = u >> 8;
            float v;
            if (j < 128) v = W[k * 128 + j] - W[(k + 128) * 128 + j];
            else         v = W[(k + 128) * 128 + (j - 128)];
            Wp[u] = rtf(v);
        } else if (t < 2 * 32768 + 128 * 144) {
            int u = t - 2 * 32768;
            int n = u & 15;
            int tap = (u >> 4) % 9;
            int o = u / 144;
            float sm = 0.f;
            for (int c = 0; c < 128; c++)
                sm += Wc[(size_t)(c * 128 + o) * 9 + tap] * Wl[c * 16 + n];
            wfold[u] = rtf(sm);
        } else if (t < PREPW) {
            int n = t - (2 * 32768 + 128 * 144);
            float sm = bl[n];
            for (int c = 0; c < 128; c++) sm += bc[c] * Wl[c * 16 + n];
            biasf[n] = sm;
        }
    }
}

// ---------------------------------------------------------------------------
// Mean pooling: one warp per superpixel; zeroes cnt_pix (self-clean).
// ---------------------------------------------------------------------------
__global__ void k_pool(const float* __restrict__ x, int* __restrict__ cnt,
                       const int* __restrict__ lst, float* __restrict__ sp) {
    int w = (blockIdx.x * blockDim.x + threadIdx.x) >> 5;
    if (w >= NSP) return;
    int lane = threadIdx.x & 31;
    int c = cnt[w];
    if (lane == 0) cnt[w] = 0;           // self-clean for next run
    int n = c < CAP ? c : CAP;
    int base = w * CAP;
    float4 acc = make_float4(0.f, 0.f, 0.f, 0.f);
    int j = 0;
    for (; j + 4 <= n; j += 4) {
        int p0 = lst[base + j], p1 = lst[base + j + 1];
        int p2 = lst[base + j + 2], p3 = lst[base + j + 3];
        float4 v0 = ((const float4*)(x + (size_t)p0 * 128))[lane];
        float4 v1 = ((const float4*)(x + (size_t)p1 * 128))[lane];
        float4 v2 = ((const float4*)(x + (size_t)p2 * 128))[lane];
        float4 v3 = ((const float4*)(x + (size_t)p3 * 128))[lane];
        acc = f4add(acc, f4add(f4add(v0, v1), f4add(v2, v3)));
    }
    for (; j < n; j++) {
        int p = lst[base + j];
        acc = f4add(acc, ((const float4*)(x + (size_t)p * 128))[lane]);
    }
    float inv = 1.0f / fmaxf((float)c, 1.0f);
    acc.x *= inv; acc.y *= inv; acc.z *= inv; acc.w *= inv;
    ((float4*)(sp + (size_t)w * 128))[lane] = r4(acc);
}

// ---------------------------------------------------------------------------
// TF32 GEMM, cp.async 2-stage pipeline, 8 warps (measured-good R10 version).
// ---------------------------------------------------------------------------
#define CPA(dst, src, sz) \
    asm volatile("cp.async.cg.shared.global [%0], [%1], 16, %2;" \
                 :: "r"(dst), "l"(src), "r"(sz))

__global__ void k_gemm_tc(const float* __restrict__ A, const float* __restrict__ B,
                          float* __restrict__ Cm, int M, int N) {
    extern __shared__ unsigned smw[];
    int tid = threadIdx.x;
    int warp = tid >> 5, lane = tid & 31;
    int g = lane >> 2, t = lane & 3;
    int wm = warp & 3, wn = warp >> 2;
    int row0 = blockIdx.y * 128, col0 = blockIdx.x * 64;

    int ar = tid >> 3, af = tid & 7;
    int br = tid >> 4, bf = tid & 15;
    int bgc = col0 + bf * 4;
    int bsz = (bgc < N) ? 16 : 0;
    int bgcc = (bgc < N) ? bgc : 0;
    const float* aSrc = A + (size_t)(row0 + ar) * 128 + af * 4;
    const float* bSrc = B + (size_t)br * N + bgcc;

    unsigned sbase = (unsigned)__cvta_generic_to_shared(smw);
    unsigned aDst0 = sbase + (unsigned)(ar * 36 + af * 4) * 4;
    unsigned bDst0 = sbase + (unsigned)(9216 + br * 72 + bf * 4) * 4;

#pragma unroll
    for (int it = 0; it < 4; it++)
        CPA(aDst0 + it * (32 * 36 * 4), aSrc + it * 32 * 128, 16);
#pragma unroll
    for (int it = 0; it < 2; it++)
        CPA(bDst0 + it * (16 * 72 * 4), bSrc + (size_t)(it * 16) * N, bsz);
    asm volatile("cp.async.commit_group;");

    float c[2][4][4] = {};
#pragma unroll
    for (int k0i = 0; k0i < 4; k0i++) {
        if (k0i < 3) {
            int s1 = (k0i + 1) & 1;
            int k1 = (k0i + 1) * 32;
            unsigned aD = aDst0 + s1 * (4608 * 4);
            unsigned bD = bDst0 + s1 * (2304 * 4);
#pragma unroll
            for (int it = 0; it < 4; it++)
                CPA(aD + it * (32 * 36 * 4), aSrc + it * 32 * 128 + k1, 16);
#pragma unroll
            for (int it = 0; it < 2; it++)
                CPA(bD + it * (16 * 72 * 4), bSrc + (size_t)(k1 + it * 16) * N, bsz);
            asm volatile("cp.async.commit_group;");
            asm volatile("cp.async.wait_group 1;");
        } else {
            asm volatile("cp.async.wait_group 0;");
        }
        __syncthreads();

        const unsigned* As = smw + (k0i & 1) * 4608;
        const unsigned* Bs = smw + 9216 + (k0i & 1) * 2304;
#pragma unroll
        for (int ks = 0; ks < 4; ks++) {
            int kk = ks * 8;
            unsigned a[2][4], b[4][2];
#pragma unroll
            for (int i = 0; i < 2; i++) {
                int rm = wm * 32 + i * 16;
                a[i][0] = As[(rm + g) * 36 + kk + t];
                a[i][1] = As[(rm + g + 8) * 36 + kk + t];
                a[i][2] = As[(rm + g) * 36 + kk + t + 4];
                a[i][3] = As[(rm + g + 8) * 36 + kk + t + 4];
            }
#pragma unroll
            for (int j = 0; j < 4; j++) {
                int cn = wn * 32 + j * 8 + g;
                b[j][0] = Bs[(kk + t) * 72 + cn];
                b[j][1] = Bs[(kk + t + 4) * 72 + cn];
            }
#pragma unroll
            for (int i = 0; i < 2; i++)
#pragma unroll
                for (int j = 0; j < 4; j++) {
                    asm volatile(
                        "mma.sync.aligned.m16n8k8.row.col.f32.tf32.tf32.f32 "
                        "{%0,%1,%2,%3}, {%4,%5,%6,%7}, {%8,%9}, {%0,%1,%2,%3};"
                        : "+f"(c[i][j][0]), "+f"(c[i][j][1]),
                          "+f"(c[i][j][2]), "+f"(c[i][j][3])
                        : "r"(a[i][0]), "r"(a[i][1]), "r"(a[i][2]), "r"(a[i][3]),
                          "r"(b[j][0]), "r"(b[j][1]));
                }
        }
        __syncthreads();
    }
#pragma unroll
    for (int i = 0; i < 2; i++) {
        int r = row0 + wm * 32 + i * 16 + g;
#pragma unroll
        for (int j = 0; j < 4; j++) {
            int cc = col0 + wn * 32 + j * 8 + 2 * t;
            if (cc < N) {
                *(float2*)(Cm + (size_t)r * N + cc) = make_float2(c[i][j][0], c[i][j][1]);
                *(float2*)(Cm + (size_t)(r + 8) * N + cc) = make_float2(c[i][j][2], c[i][j][3]);
            }
        }
    }
}

// ---------------------------------------------------------------------------
// Segmented max + relu. accum: 0 init, 1 +=, 2 final round + zero cnt_e.
// ---------------------------------------------------------------------------
__global__ void k_segmax(const float* __restrict__ AB, const float* __restrict__ bias,
                         int* __restrict__ cnt, const int* __restrict__ lst,
                         float* __restrict__ hout, float* __restrict__ h4, int accum) {
    int w = (blockIdx.x * blockDim.x + threadIdx.x) >> 5;
    if (w >= NSP) return;
    int lane = threadIdx.x & 31;
    int c = cnt[w];
    if (accum == 2 && lane == 0) cnt[w] = 0;   // self-clean for next run
    int n = c < CAP ? c : CAP;
    int base = w * CAP;
    float4 mv = make_float4(-INFINITY, -INFINITY, -INFINITY, -INFINITY);
    int j = 0;
    for (; j + 4 <= n; j += 4) {
        int s0 = lst[base + j], s1 = lst[base + j + 1];
        int s2 = lst[base + j + 2], s3 = lst[base + j + 3];
        float4 v0 = ((const float4*)(AB + (size_t)s0 * 256 + 128))[lane];
        float4 v1 = ((const float4*)(AB + (size_t)s1 * 256 + 128))[lane];
        float4 v2 = ((const float4*)(AB + (size_t)s2 * 256 + 128))[lane];
        float4 v3 = ((const float4*)(AB + (size_t)s3 * 256 + 128))[lane];
        mv = f4max(mv, f4max(f4max(v0, v1), f4max(v2, v3)));
    }
    for (; j < n; j++) {
        int s0 = lst[base + j];
        mv = f4max(mv, ((const float4*)(AB + (size_t)s0 * 256 + 128))[lane]);
    }
    float4 a  = ((const float4*)(AB + (size_t)w * 256))[lane];
    float4 bb = ((const float4*)bias)[lane];
    float4 o = make_float4(fmaxf(0.f, a.x + bb.x + mv.x),
                           fmaxf(0.f, a.y + bb.y + mv.y),
                           fmaxf(0.f, a.z + bb.z + mv.z),
                           fmaxf(0.f, a.w + bb.w + mv.w));
    ((float4*)(hout + (size_t)w * 128))[lane] = r4(o);
    float4* hp = (float4*)(h4 + (size_t)w * 128);
    if (accum == 0)      hp[lane] = o;
    else if (accum == 1) { float4 tt = hp[lane]; hp[lane] = f4add(tt, o); }
    else                 { float4 tt = hp[lane]; hp[lane] = r4(f4add(tt, o)); }
}

// ---------------------------------------------------------------------------
// Final fused unpool+conv+linear: ONE thread per pixel, 16 channels.
// ---------------------------------------------------------------------------
__global__ void k_out(const int* __restrict__ seg, const float* __restrict__ P,
                      const float* __restrict__ biasf, float* __restrict__ out) {
    int p = blockIdx.x * blockDim.x + threadIdx.x;
    if (p >= NPIX) return;
    int y = p >> 9, x = p & 511;
    float4 a0 = ((const float4*)biasf)[0];
    float4 a1 = ((const float4*)biasf)[1];
    float4 a2 = ((const float4*)biasf)[2];
    float4 a3 = ((const float4*)biasf)[3];
#pragma unroll
    for (int ky = 0; ky < 3; ky++) {
        int ny = y + ky - 1;
        if ((unsigned)ny >= 512u) continue;
#pragma unroll
        for (int kx = 0; kx < 3; kx++) {
            int nx = x + kx - 1;
            if ((unsigned)nx >= 512u) continue;
            int s = seg[(ny << 9) + nx];
            const float4* Pp = (const float4*)(P + (size_t)s * 144 + (ky * 3 + kx) * 16);
            a0 = f4add(a0, Pp[0]);
            a1 = f4add(a1, Pp[1]);
            a2 = f4add(a2, Pp[2]);
            a3 = f4add(a3, Pp[3]);
        }
    }
    float4* op = (float4*)(out + (size_t)p * 16);
    op[0] = a0; op[1] = a1; op[2] = a2; op[3] = a3;
}

// ---------------------------------------------------------------------------
// Launch
// ---------------------------------------------------------------------------
extern "C" void kernel_launch(void* const* d_in, const int* in_sizes, int n_in,
                              void* d_out, int out_size) {
    const float* x   = (const float*)d_in[0];
    const int*   ei  = (const int*)  d_in[1];
    const int*   seg = (const int*)  d_in[2];
    int wi = (n_in >= 12) ? 4 : 3;
    const float* W1 = (const float*)d_in[wi + 0];
    const float* b1 = (const float*)d_in[wi + 1];
    const float* W2 = (const float*)d_in[wi + 2];
    const float* b2 = (const float*)d_in[wi + 3];
    const float* Wc = (const float*)d_in[wi + 4];
    const float* bc = (const float*)d_in[wi + 5];
    const float* Wl = (const float*)d_in[wi + 6];
    const float* bl = (const float*)d_in[wi + 7];
    float* out = (float*)d_out;
    (void)in_sizes; (void)out_size;

    Scratch* s = nullptr;
    cudaGetSymbolAddress((void**)&s, g_s);

    cudaFuncSetAttribute(k_gemm_tc, cudaFuncAttributeMaxDynamicSharedMemorySize,
                         GEMM_SMEM_BYTES);

    // --- fused CSR scatter + weight prep (counters pre-zeroed/self-cleaned) ---
    k_begin<<<BEGIN_BLOCKS, 256>>>(seg, s->cnt_pix, s->pix_lst,
                                   ei, s->cnt_e, s->src_lst,
                                   W1, s->wp1, W2, s->wp2,
                                   Wc, Wl, bc, bl, s->wfold, s->biasf);

    // --- mean pool pixels -> superpixels (tf32-rounded; zeroes cnt_pix) ---
    k_pool<<<(NSP * 32 + 255) / 256, 256>>>(x, s->cnt_pix, s->pix_lst, s->sp);

    dim3 gAB(4, NSP / 128);
    int segGrid = (NSP * 32 + 255) / 256;
    // Layer 1: H1
    k_gemm_tc<<<gAB, 256, GEMM_SMEM_BYTES>>>(s->sp, s->wp1, s->ab, NSP, 256);
    k_segmax<<<segGrid, 256>>>(s->ab, b1, s->cnt_e, s->src_lst, s->hb0, s->h4, 0);
    // Layer 2: H2 (W2)
    k_gemm_tc<<<gAB, 256, GEMM_SMEM_BYTES>>>(s->hb0, s->wp2, s->ab, NSP, 256);
    k_segmax<<<segGrid, 256>>>(s->ab, b2, s->cnt_e, s->src_lst, s->hb1, s->h4, 1);
    // Layer 3: H3 (W2 again); h4 finalized; cnt_e self-cleaned
    k_gemm_tc<<<gAB, 256, GEMM_SMEM_BYTES>>>(s->hb1, s->wp2, s->ab, NSP, 256);
    k_segmax<<<segGrid, 256>>>(s->ab, b2, s->cnt_e, s->src_lst, s->hb0, s->h4, 2);

    // --- P = H4 @ Wfold ---
    dim3 gP(3, NSP / 128);
    k_gemm_tc<<<gP, 256, GEMM_SMEM_BYTES>>>(s->h4, s->wfold, s->P, NSP, 144);

    // --- final fused unpool + 3x3 conv + linear (1 thread/pixel) ---
    k_out<<<NPIX / 256, 256>>>(seg, s->P, s->biasf, out);
}

// round 12
// speedup vs baseline: 1.4038x; 1.4038x over previous
#include <cuda_runtime.h>
#include <math.h>

#define NSP   16384
#define NPIX  (512*512)
#define NE    262144
#define CAP   64        // max entries per segment (mean 16, 12-sigma bound)

// GEMM dynamic smem: 2 stages of As[128][36] + Bs[32][72] (unsigned words)
#define GEMM_SMEM_WORDS (2*128*36 + 2*32*72)
#define GEMM_SMEM_BYTES (GEMM_SMEM_WORDS * 4)

// ---------------------------------------------------------------------------
// Static scratch (no allocations allowed)
// ---------------------------------------------------------------------------
struct __align__(256) Scratch {
    float sp [NSP * 128];     // pooled superpixel features (tf32-rounded)
    float hb0[NSP * 128];     // layer ping (tf32-rounded)
    float hb1[NSP * 128];     // layer pong (tf32-rounded)
    float h4 [NSP * 128];     // H1+H2+H3 (tf32-rounded at final write)
    float ab [NSP * 256];     // per-node [A | B] for current layer
    float wp1[128 * 256];     // W1 folded (tf32-rounded)
    float wp2[128 * 256];     // W2 folded (tf32-rounded)
    float wfold[128 * 144];   // folded conv*linear (tf32-rounded)
    float biasf[16];          // bc@Wl + bl (full precision)
    float P  [NSP * 144];     // per-superpixel tap contributions
    int cnt_pix[NSP];         // per-sp pixel count
    int cnt_e  [NSP];         // per-sp in-edge count
    int pix_lst[NSP * CAP];   // padded CSR: pixels
    int src_lst[NSP * CAP];   // padded CSR: edge srcs
};
__device__ Scratch g_s;

// ---------------------------------------------------------------------------
// Small helpers
// ---------------------------------------------------------------------------
__device__ __forceinline__ float4 f4max(float4 a, float4 b) {
    return make_float4(fmaxf(a.x, b.x), fmaxf(a.y, b.y),
                       fmaxf(a.z, b.z), fmaxf(a.w, b.w));
}
__device__ __forceinline__ float4 f4add(float4 a, float4 b) {
    return make_float4(a.x + b.x, a.y + b.y, a.z + b.z, a.w + b.w);
}
__device__ __forceinline__ unsigned f2tf32(float f) {
    unsigned u;
    asm("cvt.rna.tf32.f32 %0, %1;" : "=r"(u) : "f"(f));
    return u;
}
__device__ __forceinline__ float rtf(float f) {
    return __uint_as_float(f2tf32(f));
}
__device__ __forceinline__ float4 r4(float4 v) {
    return make_float4(rtf(v.x), rtf(v.y), rtf(v.z), rtf(v.w));
}

// ---------------------------------------------------------------------------
// Fused prep: zero counters + wp1/wp2 + wfold (tf32-rounded) + biasf
// ---------------------------------------------------------------------------
__global__ void k_prep(int* __restrict__ cnts,
                       const float* __restrict__ W1, float* __restrict__ Wp1,
                       const float* __restrict__ W2, float* __restrict__ Wp2,
                       const float* __restrict__ Wc, const float* __restrict__ Wl,
                       const float* __restrict__ bc, const float* __restrict__ bl,
                       float* __restrict__ wfold, float* __restrict__ biasf) {
    int t = blockIdx.x * blockDim.x + threadIdx.x;
    if (t < 2 * NSP) {
        cnts[t] = 0;
    } else if (t < 2 * NSP + 2 * 32768) {
        int u = t - 2 * NSP;
        const float* W = (u < 32768) ? W1 : W2;
        float* Wp = (u < 32768) ? Wp1 : Wp2;
        u &= 32767;
        int j = u & 255, k = u >> 8;
        float v;
        if (j < 128) v = W[k * 128 + j] - W[(k + 128) * 128 + j];
        else         v = W[(k + 128) * 128 + (j - 128)];
        Wp[u] = rtf(v);
    } else if (t < 2 * NSP + 2 * 32768 + 128 * 144) {
        int u = t - (2 * NSP + 2 * 32768);
        int n = u & 15;
        int tap = (u >> 4) % 9;
        int o = u / 144;
        float sm = 0.f;
        for (int c = 0; c < 128; c++)
            sm += Wc[(size_t)(c * 128 + o) * 9 + tap] * Wl[c * 16 + n];
        wfold[u] = rtf(sm);
    } else if (t < 2 * NSP + 2 * 32768 + 128 * 144 + 16) {
        int n = t - (2 * NSP + 2 * 32768 + 128 * 144);
        float sm = bl[n];
        for (int c = 0; c < 128; c++) sm += bc[c] * Wl[c * 16 + n];
        biasf[n] = sm;
    }
}

// ---------------------------------------------------------------------------
// Direct scatter into padded CSR (counter = degree). One pass, no scan.
// ---------------------------------------------------------------------------
__global__ void k_scat_both(const int* __restrict__ seg, int* __restrict__ cpix,
                            int* __restrict__ plst, const int* __restrict__ ei,
                            int* __restrict__ ce, int* __restrict__ elst) {
    int i = blockIdx.x * blockDim.x + threadIdx.x;
    {
        int k = seg[i];
        int p = atomicAdd(&cpix[k], 1);
        if (p < CAP) plst[k * CAP + p] = i;
    }
    {
        int d = ei[NE + i];
        int p = atomicAdd(&ce[d], 1);
        if (p < CAP) elst[d * CAP + p] = ei[i];
    }
}

// ---------------------------------------------------------------------------
// Mean pooling: one warp per superpixel; output tf32-rounded (GEMM A input)
// ---------------------------------------------------------------------------
__global__ void k_pool(const float* __restrict__ x, const int* __restrict__ cnt,
                       const int* __restrict__ lst, float* __restrict__ sp) {
    int w = (blockIdx.x * blockDim.x + threadIdx.x) >> 5;
    if (w >= NSP) return;
    int lane = threadIdx.x & 31;
    int c = cnt[w];
    int n = c < CAP ? c : CAP;
    int base = w * CAP;
    float4 acc = make_float4(0.f, 0.f, 0.f, 0.f);
    int j = 0;
    for (; j + 4 <= n; j += 4) {
        int p0 = lst[base + j], p1 = lst[base + j + 1];
        int p2 = lst[base + j + 2], p3 = lst[base + j + 3];
        float4 v0 = ((const float4*)(x + (size_t)p0 * 128))[lane];
        float4 v1 = ((const float4*)(x + (size_t)p1 * 128))[lane];
        float4 v2 = ((const float4*)(x + (size_t)p2 * 128))[lane];
        float4 v3 = ((const float4*)(x + (size_t)p3 * 128))[lane];
        acc = f4add(acc, f4add(f4add(v0, v1), f4add(v2, v3)));
    }
    for (; j < n; j++) {
        int p = lst[base + j];
        acc = f4add(acc, ((const float4*)(x + (size_t)p * 128))[lane]);
    }
    float inv = 1.0f / fmaxf((float)c, 1.0f);
    acc.x *= inv; acc.y *= inv; acc.z *= inv; acc.w *= inv;
    ((float4*)(sp + (size_t)w * 128))[lane] = r4(acc);
}

// ---------------------------------------------------------------------------
// TF32 GEMM, cp.async 2-stage pipeline, 8 warps (measured-good R10 version).
// ---------------------------------------------------------------------------
#define CPA(dst, src, sz) \
    asm volatile("cp.async.cg.shared.global [%0], [%1], 16, %2;" \
                 :: "r"(dst), "l"(src), "r"(sz))

__global__ void k_gemm_tc(const float* __restrict__ A, const float* __restrict__ B,
                          float* __restrict__ Cm, int M, int N) {
    extern __shared__ unsigned smw[];
    int tid = threadIdx.x;
    int warp = tid >> 5, lane = tid & 31;
    int g = lane >> 2, t = lane & 3;
    int wm = warp & 3, wn = warp >> 2;
    int row0 = blockIdx.y * 128, col0 = blockIdx.x * 64;

    int ar = tid >> 3, af = tid & 7;
    int br = tid >> 4, bf = tid & 15;
    int bgc = col0 + bf * 4;
    int bsz = (bgc < N) ? 16 : 0;
    int bgcc = (bgc < N) ? bgc : 0;
    const float* aSrc = A + (size_t)(row0 + ar) * 128 + af * 4;
    const float* bSrc = B + (size_t)br * N + bgcc;

    unsigned sbase = (unsigned)__cvta_generic_to_shared(smw);
    unsigned aDst0 = sbase + (unsigned)(ar * 36 + af * 4) * 4;
    unsigned bDst0 = sbase + (unsigned)(9216 + br * 72 + bf * 4) * 4;

#pragma unroll
    for (int it = 0; it < 4; it++)
        CPA(aDst0 + it * (32 * 36 * 4), aSrc + it * 32 * 128, 16);
#pragma unroll
    for (int it = 0; it < 2; it++)
        CPA(bDst0 + it * (16 * 72 * 4), bSrc + (size_t)(it * 16) * N, bsz);
    asm volatile("cp.async.commit_group;");

    float c[2][4][4] = {};
#pragma unroll
    for (int k0i = 0; k0i < 4; k0i++) {
        if (k0i < 3) {
            int s1 = (k0i + 1) & 1;
            int k1 = (k0i + 1) * 32;
            unsigned aD = aDst0 + s1 * (4608 * 4);
            unsigned bD = bDst0 + s1 * (2304 * 4);
#pragma unroll
            for (int it = 0; it < 4; it++)
                CPA(aD + it * (32 * 36 * 4), aSrc + it * 32 * 128 + k1, 16);
#pragma unroll
            for (int it = 0; it < 2; it++)
                CPA(bD + it * (16 * 72 * 4), bSrc + (size_t)(k1 + it * 16) * N, bsz);
            asm volatile("cp.async.commit_group;");
            asm volatile("cp.async.wait_group 1;");
        } else {
            asm volatile("cp.async.wait_group 0;");
        }
        __syncthreads();

        const unsigned* As = smw + (k0i & 1) * 4608;
        const unsigned* Bs = smw + 9216 + (k0i & 1) * 2304;
#pragma unroll
        for (int ks = 0; ks < 4; ks++) {
            int kk = ks * 8;
            unsigned a[2][4], b[4][2];
#pragma unroll
            for (int i = 0; i < 2; i++) {
                int rm = wm * 32 + i * 16;
                a[i][0] = As[(rm + g) * 36 + kk + t];
                a[i][1] = As[(rm + g + 8) * 36 + kk + t];
                a[i][2] = As[(rm + g) * 36 + kk + t + 4];
                a[i][3] = As[(rm + g + 8) * 36 + kk + t + 4];
            }
#pragma unroll
            for (int j = 0; j < 4; j++) {
                int cn = wn * 32 + j * 8 + g;
                b[j][0] = Bs[(kk + t) * 72 + cn];
                b[j][1] = Bs[(kk + t + 4) * 72 + cn];
            }
#pragma unroll
            for (int i = 0; i < 2; i++)
#pragma unroll
                for (int j = 0; j < 4; j++) {
                    asm volatile(
                        "mma.sync.aligned.m16n8k8.row.col.f32.tf32.tf32.f32 "
                        "{%0,%1,%2,%3}, {%4,%5,%6,%7}, {%8,%9}, {%0,%1,%2,%3};"
                        : "+f"(c[i][j][0]), "+f"(c[i][j][1]),
                          "+f"(c[i][j][2]), "+f"(c[i][j][3])
                        : "r"(a[i][0]), "r"(a[i][1]), "r"(a[i][2]), "r"(a[i][3]),
                          "r"(b[j][0]), "r"(b[j][1]));
                }
        }
        __syncthreads();
    }
#pragma unroll
    for (int i = 0; i < 2; i++) {
        int r = row0 + wm * 32 + i * 16 + g;
#pragma unroll
        for (int j = 0; j < 4; j++) {
            int cc = col0 + wn * 32 + j * 8 + 2 * t;
            if (cc < N) {
                *(float2*)(Cm + (size_t)r * N + cc) = make_float2(c[i][j][0], c[i][j][1]);
                *(float2*)(Cm + (size_t)(r + 8) * N + cc) = make_float2(c[i][j][2], c[i][j][3]);
            }
        }
    }
}

// ---------------------------------------------------------------------------
// Segmented max + relu, HIGH-MLP gather: src indices preloaded into lane regs
// (2 coalesced loads), distributed via shfl; gather loop unrolled x8.
// accum: 0 = h4 init, 1 = h4 +=, 2 = h4 = round(h4 + o) [final].
// ---------------------------------------------------------------------------
__global__ void k_segmax(const float* __restrict__ AB, const float* __restrict__ bias,
                         const int* __restrict__ cnt, const int* __restrict__ lst,
                         float* __restrict__ hout, float* __restrict__ h4, int accum) {
    int w = (blockIdx.x * blockDim.x + threadIdx.x) >> 5;
    if (w >= NSP) return;
    int lane = threadIdx.x & 31;
    int c = cnt[w];
    int n = c < CAP ? c : CAP;
    int base = w * CAP;
    // preload all indices (coalesced, 2 loads per lane max)
    int idxA = (lane < n)      ? lst[base + lane]      : 0;
    int idxB = (32 + lane < n) ? lst[base + 32 + lane] : 0;

    float4 mv = make_float4(-INFINITY, -INFINITY, -INFINITY, -INFINITY);
    int j = 0;
    for (; j + 8 <= n; j += 8) {
        float4 v[8];
#pragma unroll
        for (int u = 0; u < 8; u++) {
            int jj = j + u;
            int s0 = __shfl_sync(~0u, jj < 32 ? idxA : idxB, jj & 31);
            v[u] = ((const float4*)(AB + (size_t)s0 * 256 + 128))[lane];
        }
#pragma unroll
        for (int u = 0; u < 8; u++) mv = f4max(mv, v[u]);
    }
    for (; j < n; j++) {
        int s0 = __shfl_sync(~0u, j < 32 ? idxA : idxB, j & 31);
        mv = f4max(mv, ((const float4*)(AB + (size_t)s0 * 256 + 128))[lane]);
    }
    float4 a  = ((const float4*)(AB + (size_t)w * 256))[lane];
    float4 bb = ((const float4*)bias)[lane];
    float4 o = make_float4(fmaxf(0.f, a.x + bb.x + mv.x),
                           fmaxf(0.f, a.y + bb.y + mv.y),
                           fmaxf(0.f, a.z + bb.z + mv.z),
                           fmaxf(0.f, a.w + bb.w + mv.w));
    ((float4*)(hout + (size_t)w * 128))[lane] = r4(o);
    float4* hp = (float4*)(h4 + (size_t)w * 128);
    if (accum == 0)      hp[lane] = o;
    else if (accum == 1) { float4 tt = hp[lane]; hp[lane] = f4add(tt, o); }
    else                 { float4 tt = hp[lane]; hp[lane] = r4(f4add(tt, o)); }
}

// ---------------------------------------------------------------------------
// Final fused unpool+conv+linear: 4 threads per pixel, 4 channels each.
// ---------------------------------------------------------------------------
__global__ void k_out(const int* __restrict__ seg, const float* __restrict__ P,
                      const float* __restrict__ biasf, float* __restrict__ out) {
    int gidx = blockIdx.x * blockDim.x + threadIdx.x;
    if (gidx >= NPIX * 4) return;
    int p = gidx >> 2, q = gidx & 3;
    int y = p >> 9, x = p & 511;
    float4 acc = ((const float4*)biasf)[q];
#pragma unroll
    for (int ky = 0; ky < 3; ky++) {
        int ny = y + ky - 1;
        if ((unsigned)ny >= 512u) continue;
#pragma unroll
        for (int kx = 0; kx < 3; kx++) {
            int nx = x + kx - 1;
            if ((unsigned)nx >= 512u) continue;
            int s = seg[(ny << 9) + nx];
            float4 v = ((const float4*)(P + (size_t)s * 144 + (ky * 3 + kx) * 16))[q];
            acc = f4add(acc, v);
        }
    }
    ((float4*)out)[gidx] = acc;
}

// ---------------------------------------------------------------------------
// Launch
// ---------------------------------------------------------------------------
extern "C" void kernel_launch(void* const* d_in, const int* in_sizes, int n_in,
                              void* d_out, int out_size) {
    const float* x   = (const float*)d_in[0];
    const int*   ei  = (const int*)  d_in[1];
    const int*   seg = (const int*)  d_in[2];
    int wi = (n_in >= 12) ? 4 : 3;
    const float* W1 = (const float*)d_in[wi + 0];
    const float* b1 = (const float*)d_in[wi + 1];
    const float* W2 = (const float*)d_in[wi + 2];
    const float* b2 = (const float*)d_in[wi + 3];
    const float* Wc = (const float*)d_in[wi + 4];
    const float* bc = (const float*)d_in[wi + 5];
    const float* Wl = (const float*)d_in[wi + 6];
    const float* bl = (const float*)d_in[wi + 7];
    float* out = (float*)d_out;
    (void)in_sizes; (void)out_size;

    Scratch* s = nullptr;
    cudaGetSymbolAddress((void**)&s, g_s);

    cudaFuncSetAttribute(k_gemm_tc, cudaFuncAttributeMaxDynamicSharedMemorySize,
                         GEMM_SMEM_BYTES);

    // --- fused prep: zero counters + all weight folds (tf32-rounded) ---
    int prepN = 2 * NSP + 2 * 32768 + 128 * 144 + 16;
    k_prep<<<(prepN + 255) / 256, 256>>>(s->cnt_pix, W1, s->wp1, W2, s->wp2,
                                         Wc, Wl, bc, bl, s->wfold, s->biasf);

    // --- direct padded-CSR scatter ---
    k_scat_both<<<NPIX / 256, 256>>>(seg, s->cnt_pix, s->pix_lst,
                                     ei, s->cnt_e, s->src_lst);

    // --- mean pool pixels -> superpixels (tf32-rounded) ---
    k_pool<<<(NSP * 32 + 255) / 256, 256>>>(x, s->cnt_pix, s->pix_lst, s->sp);

    dim3 gAB(4, NSP / 128);
    int segGrid = (NSP * 32 + 255) / 256;
    // Layer 1: H1
    k_gemm_tc<<<gAB, 256, GEMM_SMEM_BYTES>>>(s->sp, s->wp1, s->ab, NSP, 256);
    k_segmax<<<segGrid, 256>>>(s->ab, b1, s->cnt_e, s->src_lst, s->hb0, s->h4, 0);
    // Layer 2: H2 (W2)
    k_gemm_tc<<<gAB, 256, GEMM_SMEM_BYTES>>>(s->hb0, s->wp2, s->ab, NSP, 256);
    k_segmax<<<segGrid, 256>>>(s->ab, b2, s->cnt_e, s->src_lst, s->hb1, s->h4, 1);
    // Layer 3: H3 (W2 again); h4 finalized tf32-rounded
    k_gemm_tc<<<gAB, 256, GEMM_SMEM_BYTES>>>(s->hb1, s->wp2, s->ab, NSP, 256);
    k_segmax<<<segGrid, 256>>>(s->ab, b2, s->cnt_e, s->src_lst, s->hb0, s->h4, 2);

    // --- P = H4 @ Wfold ---
    dim3 gP(3, NSP / 128);
    k_gemm_tc<<<gP, 256, GEMM_SMEM_BYTES>>>(s->h4, s->wfold, s->P, NSP, 144);

    // --- final fused unpool + 3x3 conv + linear ---
    k_out<<<(NPIX * 4 + 255) / 256, 256>>>(seg, s->P, s->biasf, out);
}

// round 13
// speedup vs baseline: 1.4528x; 1.0349x over previous
#include <cuda_runtime.h>
#include <cuda_fp16.h>
#include <math.h>

#define NSP   16384
#define NPIX  (512*512)
#define NE    262144
#define CAP   64        // max entries per segment (mean 16, 12-sigma bound)

// GEMM dynamic smem: 2 stages of As[128][36] + Bs[32][72] (unsigned words)
#define GEMM_SMEM_WORDS (2*128*36 + 2*32*72)
#define GEMM_SMEM_BYTES (GEMM_SMEM_WORDS * 4)

// ---------------------------------------------------------------------------
// Static scratch (no allocations allowed)
// ---------------------------------------------------------------------------
struct __align__(256) Scratch {
    float sp [NSP * 128];     // pooled superpixel features (tf32-rounded)
    float hb0[NSP * 128];     // layer ping (tf32-rounded)
    float hb1[NSP * 128];     // layer pong (tf32-rounded)
    float h4 [NSP * 128];     // H1+H2+H3 (tf32-rounded at final write)
    float abA[NSP * 128];     // per-node A-half (fp32)
    __half abB[NSP * 128];    // per-node B-half (fp16, gathered by segmax)
    float wp1[128 * 256];     // W1 folded (tf32-rounded)
    float wp2[128 * 256];     // W2 folded (tf32-rounded)
    float wfold[128 * 144];   // folded conv*linear (tf32-rounded)
    float biasf[16];          // bc@Wl + bl (full precision)
    float P  [NSP * 144];     // per-superpixel tap contributions
    int cnt_pix[NSP];         // per-sp pixel count
    int cnt_e  [NSP];         // per-sp in-edge count
    int pix_lst[NSP * CAP];   // padded CSR: pixels
    int src_lst[NSP * CAP];   // padded CSR: edge srcs
};
__device__ Scratch g_s;

// ---------------------------------------------------------------------------
// Small helpers
// ---------------------------------------------------------------------------
__device__ __forceinline__ float4 f4max(float4 a, float4 b) {
    return make_float4(fmaxf(a.x, b.x), fmaxf(a.y, b.y),
                       fmaxf(a.z, b.z), fmaxf(a.w, b.w));
}
__device__ __forceinline__ float4 f4add(float4 a, float4 b) {
    return make_float4(a.x + b.x, a.y + b.y, a.z + b.z, a.w + b.w);
}
__device__ __forceinline__ unsigned f2tf32(float f) {
    unsigned u;
    asm("cvt.rna.tf32.f32 %0, %1;" : "=r"(u) : "f"(f));
    return u;
}
__device__ __forceinline__ float rtf(float f) {
    return __uint_as_float(f2tf32(f));
}
__device__ __forceinline__ float4 r4(float4 v) {
    return make_float4(rtf(v.x), rtf(v.y), rtf(v.z), rtf(v.w));
}
__device__ __forceinline__ float4 h4tof4(uint2 u) {
    __half2 h0 = *reinterpret_cast<__half2*>(&u.x);
    __half2 h1 = *reinterpret_cast<__half2*>(&u.y);
    float2 f0 = __half22float2(h0), f1 = __half22float2(h1);
    return make_float4(f0.x, f0.y, f1.x, f1.y);
}

// ---------------------------------------------------------------------------
// Fused prep: zero counters + wp1/wp2 + wfold (tf32-rounded) + biasf
// ---------------------------------------------------------------------------
__global__ void k_prep(int* __restrict__ cnts,
                       const float* __restrict__ W1, float* __restrict__ Wp1,
                       const float* __restrict__ W2, float* __restrict__ Wp2,
                       const float* __restrict__ Wc, const float* __restrict__ Wl,
                       const float* __restrict__ bc, const float* __restrict__ bl,
                       float* __restrict__ wfold, float* __restrict__ biasf) {
    int t = blockIdx.x * blockDim.x + threadIdx.x;
    if (t < 2 * NSP) {
        cnts[t] = 0;
    } else if (t < 2 * NSP + 2 * 32768) {
        int u = t - 2 * NSP;
        const float* W = (u < 32768) ? W1 : W2;
        float* Wp = (u < 32768) ? Wp1 : Wp2;
        u &= 32767;
        int j = u & 255, k = u >> 8;
        float v;
        if (j < 128) v = W[k * 128 + j] - W[(k + 128) * 128 + j];
        else         v = W[(k + 128) * 128 + (j - 128)];
        Wp[u] = rtf(v);
    } else if (t < 2 * NSP + 2 * 32768 + 128 * 144) {
        int u = t - (2 * NSP + 2 * 32768);
        int n = u & 15;
        int tap = (u >> 4) % 9;
        int o = u / 144;
        float sm = 0.f;
        for (int c = 0; c < 128; c++)
            sm += Wc[(size_t)(c * 128 + o) * 9 + tap] * Wl[c * 16 + n];
        wfold[u] = rtf(sm);
    } else if (t < 2 * NSP + 2 * 32768 + 128 * 144 + 16) {
        int n = t - (2 * NSP + 2 * 32768 + 128 * 144);
        float sm = bl[n];
        for (int c = 0; c < 128; c++) sm += bc[c] * Wl[c * 16 + n];
        biasf[n] = sm;
    }
}

// ---------------------------------------------------------------------------
// Direct scatter into padded CSR (counter = degree). One pass, no scan.
// ---------------------------------------------------------------------------
__global__ void k_scat_both(const int* __restrict__ seg, int* __restrict__ cpix,
                            int* __restrict__ plst, const int* __restrict__ ei,
                            int* __restrict__ ce, int* __restrict__ elst) {
    int i = blockIdx.x * blockDim.x + threadIdx.x;
    {
        int k = seg[i];
        int p = atomicAdd(&cpix[k], 1);
        if (p < CAP) plst[k * CAP + p] = i;
    }
    {
        int d = ei[NE + i];
        int p = atomicAdd(&ce[d], 1);
        if (p < CAP) elst[d * CAP + p] = ei[i];
    }
}

// ---------------------------------------------------------------------------
// Mean pooling: one warp per superpixel; output tf32-rounded (GEMM A input)
// ---------------------------------------------------------------------------
__global__ void k_pool(const float* __restrict__ x, const int* __restrict__ cnt,
                       const int* __restrict__ lst, float* __restrict__ sp) {
    int w = (blockIdx.x * blockDim.x + threadIdx.x) >> 5;
    if (w >= NSP) return;
    int lane = threadIdx.x & 31;
    int c = cnt[w];
    int n = c < CAP ? c : CAP;
    int base = w * CAP;
    float4 acc = make_float4(0.f, 0.f, 0.f, 0.f);
    int j = 0;
    for (; j + 4 <= n; j += 4) {
        int p0 = lst[base + j], p1 = lst[base + j + 1];
        int p2 = lst[base + j + 2], p3 = lst[base + j + 3];
        float4 v0 = ((const float4*)(x + (size_t)p0 * 128))[lane];
        float4 v1 = ((const float4*)(x + (size_t)p1 * 128))[lane];
        float4 v2 = ((const float4*)(x + (size_t)p2 * 128))[lane];
        float4 v3 = ((const float4*)(x + (size_t)p3 * 128))[lane];
        acc = f4add(acc, f4add(f4add(v0, v1), f4add(v2, v3)));
    }
    for (; j < n; j++) {
        int p = lst[base + j];
        acc = f4add(acc, ((const float4*)(x + (size_t)p * 128))[lane]);
    }
    float inv = 1.0f / fmaxf((float)c, 1.0f);
    acc.x *= inv; acc.y *= inv; acc.z *= inv; acc.w *= inv;
    ((float4*)(sp + (size_t)w * 128))[lane] = r4(acc);
}

// ---------------------------------------------------------------------------
// TF32 GEMM, cp.async 2-stage pipeline, 8 warps (R10/R12 core).
// mode 0: plain fp32 C[M,N] (row stride N).
// mode 1: split epilogue — cols<128 -> CmA fp32 (stride 128);
//         cols>=128 -> CmB fp16 (stride 128). N must be 256.
// ---------------------------------------------------------------------------
#define CPA(dst, src, sz) \
    asm volatile("cp.async.cg.shared.global [%0], [%1], 16, %2;" \
                 :: "r"(dst), "l"(src), "r"(sz))

__global__ void k_gemm_tc(const float* __restrict__ A, const float* __restrict__ B,
                          float* __restrict__ Cm, __half* __restrict__ CmB,
                          int M, int N, int mode) {
    extern __shared__ unsigned smw[];
    int tid = threadIdx.x;
    int warp = tid >> 5, lane = tid & 31;
    int g = lane >> 2, t = lane & 3;
    int wm = warp & 3, wn = warp >> 2;
    int row0 = blockIdx.y * 128, col0 = blockIdx.x * 64;

    int ar = tid >> 3, af = tid & 7;
    int br = tid >> 4, bf = tid & 15;
    int bgc = col0 + bf * 4;
    int bsz = (bgc < N) ? 16 : 0;
    int bgcc = (bgc < N) ? bgc : 0;
    const float* aSrc = A + (size_t)(row0 + ar) * 128 + af * 4;
    const float* bSrc = B + (size_t)br * N + bgcc;

    unsigned sbase = (unsigned)__cvta_generic_to_shared(smw);
    unsigned aDst0 = sbase + (unsigned)(ar * 36 + af * 4) * 4;
    unsigned bDst0 = sbase + (unsigned)(9216 + br * 72 + bf * 4) * 4;

#pragma unroll
    for (int it = 0; it < 4; it++)
        CPA(aDst0 + it * (32 * 36 * 4), aSrc + it * 32 * 128, 16);
#pragma unroll
    for (int it = 0; it < 2; it++)
        CPA(bDst0 + it * (16 * 72 * 4), bSrc + (size_t)(it * 16) * N, bsz);
    asm volatile("cp.async.commit_group;");

    float c[2][4][4] = {};
#pragma unroll
    for (int k0i = 0; k0i < 4; k0i++) {
        if (k0i < 3) {
            int s1 = (k0i + 1) & 1;
            int k1 = (k0i + 1) * 32;
            unsigned aD = aDst0 + s1 * (4608 * 4);
            unsigned bD = bDst0 + s1 * (2304 * 4);
#pragma unroll
            for (int it = 0; it < 4; it++)
                CPA(aD + it * (32 * 36 * 4), aSrc + it * 32 * 128 + k1, 16);
#pragma unroll
            for (int it = 0; it < 2; it++)
                CPA(bD + it * (16 * 72 * 4), bSrc + (size_t)(k1 + it * 16) * N, bsz);
            asm volatile("cp.async.commit_group;");
            asm volatile("cp.async.wait_group 1;");
        } else {
            asm volatile("cp.async.wait_group 0;");
        }
        __syncthreads();

        const unsigned* As = smw + (k0i & 1) * 4608;
        const unsigned* Bs = smw + 9216 + (k0i & 1) * 2304;
#pragma unroll
        for (int ks = 0; ks < 4; ks++) {
            int kk = ks * 8;
            unsigned a[2][4], b[4][2];
#pragma unroll
            for (int i = 0; i < 2; i++) {
                int rm = wm * 32 + i * 16;
                a[i][0] = As[(rm + g) * 36 + kk + t];
                a[i][1] = As[(rm + g + 8) * 36 + kk + t];
                a[i][2] = As[(rm + g) * 36 + kk + t + 4];
                a[i][3] = As[(rm + g + 8) * 36 + kk + t + 4];
            }
#pragma unroll
            for (int j = 0; j < 4; j++) {
                int cn = wn * 32 + j * 8 + g;
                b[j][0] = Bs[(kk + t) * 72 + cn];
                b[j][1] = Bs[(kk + t + 4) * 72 + cn];
            }
#pragma unroll
            for (int i = 0; i < 2; i++)
#pragma unroll
                for (int j = 0; j < 4; j++) {
                    asm volatile(
                        "mma.sync.aligned.m16n8k8.row.col.f32.tf32.tf32.f32 "
                        "{%0,%1,%2,%3}, {%4,%5,%6,%7}, {%8,%9}, {%0,%1,%2,%3};"
                        : "+f"(c[i][j][0]), "+f"(c[i][j][1]),
                          "+f"(c[i][j][2]), "+f"(c[i][j][3])
                        : "r"(a[i][0]), "r"(a[i][1]), "r"(a[i][2]), "r"(a[i][3]),
                          "r"(b[j][0]), "r"(b[j][1]));
                }
        }
        __syncthreads();
    }
    if (mode == 0) {
#pragma unroll
        for (int i = 0; i < 2; i++) {
            int r = row0 + wm * 32 + i * 16 + g;
#pragma unroll
            for (int j = 0; j < 4; j++) {
                int cc = col0 + wn * 32 + j * 8 + 2 * t;
                if (cc < N) {
                    *(float2*)(Cm + (size_t)r * N + cc) = make_float2(c[i][j][0], c[i][j][1]);
                    *(float2*)(Cm + (size_t)(r + 8) * N + cc) = make_float2(c[i][j][2], c[i][j][3]);
                }
            }
        }
    } else if (col0 < 128) {
        // A-half: fp32, stride 128
#pragma unroll
        for (int i = 0; i < 2; i++) {
            int r = row0 + wm * 32 + i * 16 + g;
#pragma unroll
            for (int j = 0; j < 4; j++) {
                int cc = col0 + wn * 32 + j * 8 + 2 * t;
                *(float2*)(Cm + (size_t)r * 128 + cc) = make_float2(c[i][j][0], c[i][j][1]);
                *(float2*)(Cm + (size_t)(r + 8) * 128 + cc) = make_float2(c[i][j][2], c[i][j][3]);
            }
        }
    } else {
        // B-half: fp16, stride 128
#pragma unroll
        for (int i = 0; i < 2; i++) {
            int r = row0 + wm * 32 + i * 16 + g;
#pragma unroll
            for (int j = 0; j < 4; j++) {
                int cc2 = (col0 - 128) + wn * 32 + j * 8 + 2 * t;
                *(__half2*)(CmB + (size_t)r * 128 + cc2) =
                    __floats2half2_rn(c[i][j][0], c[i][j][1]);
                *(__half2*)(CmB + (size_t)(r + 8) * 128 + cc2) =
                    __floats2half2_rn(c[i][j][2], c[i][j][3]);
            }
        }
    }
}

// ---------------------------------------------------------------------------
// Segmented max + relu, fp16 B gather (8B/lane), high MLP (x8 unroll).
// accum: 0 = h4 init, 1 = h4 +=, 2 = h4 = round(h4 + o) [final].
// ---------------------------------------------------------------------------
__global__ void k_segmax(const float* __restrict__ Aarr, const __half* __restrict__ Barr,
                         const float* __restrict__ bias,
                         const int* __restrict__ cnt, const int* __restrict__ lst,
                         float* __restrict__ hout, float* __restrict__ h4, int accum) {
    int w = (blockIdx.x * blockDim.x + threadIdx.x) >> 5;
    if (w >= NSP) return;
    int lane = threadIdx.x & 31;
    int c = cnt[w];
    int n = c < CAP ? c : CAP;
    int base = w * CAP;
    int idxA = (lane < n)      ? lst[base + lane]      : 0;
    int idxB = (32 + lane < n) ? lst[base + 32 + lane] : 0;

    float4 mv = make_float4(-INFINITY, -INFINITY, -INFINITY, -INFINITY);
    int j = 0;
    for (; j + 8 <= n; j += 8) {
        uint2 v[8];
#pragma unroll
        for (int u = 0; u < 8; u++) {
            int jj = j + u;
            int s0 = __shfl_sync(~0u, jj < 32 ? idxA : idxB, jj & 31);
            v[u] = ((const uint2*)(Barr + (size_t)s0 * 128))[lane];
        }
#pragma unroll
        for (int u = 0; u < 8; u++) mv = f4max(mv, h4tof4(v[u]));
    }
    for (; j < n; j++) {
        int s0 = __shfl_sync(~0u, j < 32 ? idxA : idxB, j & 31);
        mv = f4max(mv, h4tof4(((const uint2*)(Barr + (size_t)s0 * 128))[lane]));
    }
    float4 a  = ((const float4*)(Aarr + (size_t)w * 128))[lane];
    float4 bb = ((const float4*)bias)[lane];
    float4 o = make_float4(fmaxf(0.f, a.x + bb.x + mv.x),
                           fmaxf(0.f, a.y + bb.y + mv.y),
                           fmaxf(0.f, a.z + bb.z + mv.z),
                           fmaxf(0.f, a.w + bb.w + mv.w));
    ((float4*)(hout + (size_t)w * 128))[lane] = r4(o);
    float4* hp = (float4*)(h4 + (size_t)w * 128);
    if (accum == 0)      hp[lane] = o;
    else if (accum == 1) { float4 tt = hp[lane]; hp[lane] = f4add(tt, o); }
    else                 { float4 tt = hp[lane]; hp[lane] = r4(f4add(tt, o)); }
}

// ---------------------------------------------------------------------------
// Final fused unpool+conv+linear: 4 threads per pixel, 4 channels each.
// ---------------------------------------------------------------------------
__global__ void k_out(const int* __restrict__ seg, const float* __restrict__ P,
                      const float* __restrict__ biasf, float* __restrict__ out) {
    int gidx = blockIdx.x * blockDim.x + threadIdx.x;
    if (gidx >= NPIX * 4) return;
    int p = gidx >> 2, q = gidx & 3;
    int y = p >> 9, x = p & 511;
    float4 acc = ((const float4*)biasf)[q];
#pragma unroll
    for (int ky = 0; ky < 3; ky++) {
        int ny = y + ky - 1;
        if ((unsigned)ny >= 512u) continue;
#pragma unroll
        for (int kx = 0; kx < 3; kx++) {
            int nx = x + kx - 1;
            if ((unsigned)nx >= 512u) continue;
            int s = seg[(ny << 9) + nx];
            float4 v = ((const float4*)(P + (size_t)s * 144 + (ky * 3 + kx) * 16))[q];
            acc = f4add(acc, v);
        }
    }
    ((float4*)out)[gidx] = acc;
}

// ---------------------------------------------------------------------------
// Launch
// ---------------------------------------------------------------------------
extern "C" void kernel_launch(void* const* d_in, const int* in_sizes, int n_in,
                              void* d_out, int out_size) {
    const float* x   = (const float*)d_in[0];
    const int*   ei  = (const int*)  d_in[1];
    const int*   seg = (const int*)  d_in[2];
    int wi = (n_in >= 12) ? 4 : 3;
    const float* W1 = (const float*)d_in[wi + 0];
    const float* b1 = (const float*)d_in[wi + 1];
    const float* W2 = (const float*)d_in[wi + 2];
    const float* b2 = (const float*)d_in[wi + 3];
    const float* Wc = (const float*)d_in[wi + 4];
    const float* bc = (const float*)d_in[wi + 5];
    const float* Wl = (const float*)d_in[wi + 6];
    const float* bl = (const float*)d_in[wi + 7];
    float* out = (float*)d_out;
    (void)in_sizes; (void)out_size;

    Scratch* s = nullptr;
    cudaGetSymbolAddress((void**)&s, g_s);

    cudaFuncSetAttribute(k_gemm_tc, cudaFuncAttributeMaxDynamicSharedMemorySize,
                         GEMM_SMEM_BYTES);

    // --- fused prep: zero counters + all weight folds (tf32-rounded) ---
    int prepN = 2 * NSP + 2 * 32768 + 128 * 144 + 16;
    k_prep<<<(prepN + 255) / 256, 256>>>(s->cnt_pix, W1, s->wp1, W2, s->wp2,
                                         Wc, Wl, bc, bl, s->wfold, s->biasf);

    // --- direct padded-CSR scatter ---
    k_scat_both<<<NPIX / 256, 256>>>(seg, s->cnt_pix, s->pix_lst,
                                     ei, s->cnt_e, s->src_lst);

    // --- mean pool pixels -> superpixels (tf32-rounded) ---
    k_pool<<<(NSP * 32 + 255) / 256, 256>>>(x, s->cnt_pix, s->pix_lst, s->sp);

    dim3 gAB(4, NSP / 128);
    int segGrid = (NSP * 32 + 255) / 256;
    // Layer 1: H1
    k_gemm_tc<<<gAB, 256, GEMM_SMEM_BYTES>>>(s->sp, s->wp1, s->abA, s->abB,
                                             NSP, 256, 1);
    k_segmax<<<segGrid, 256>>>(s->abA, s->abB, b1, s->cnt_e, s->src_lst,
                               s->hb0, s->h4, 0);
    // Layer 2: H2 (W2)
    k_gemm_tc<<<gAB, 256, GEMM_SMEM_BYTES>>>(s->hb0, s->wp2, s->abA, s->abB,
                                             NSP, 256, 1);
    k_segmax<<<segGrid, 256>>>(s->abA, s->abB, b2, s->cnt_e, s->src_lst,
                               s->hb1, s->h4, 1);
    // Layer 3: H3 (W2 again); h4 finalized tf32-rounded
    k_gemm_tc<<<gAB, 256, GEMM_SMEM_BYTES>>>(s->hb1, s->wp2, s->abA, s->abB,
                                             NSP, 256, 1);
    k_segmax<<<segGrid, 256>>>(s->abA, s->abB, b2, s->cnt_e, s->src_lst,
                               s->hb0, s->h4, 2);

    // --- P = H4 @ Wfold ---
    dim3 gP(3, NSP / 128);
    k_gemm_tc<<<gP, 256, GEMM_SMEM_BYTES>>>(s->h4, s->wfold, s->P, nullptr,
                                            NSP, 144, 0);

    // --- final fused unpool + 3x3 conv + linear ---
    k_out<<<(NPIX * 4 + 255) / 256, 256>>>(seg, s->P, s->biasf, out);
}

// round 14
// speedup vs baseline: 1.6121x; 1.1096x over previous
#include <cuda_runtime.h>
#include <cuda_fp16.h>
#include <math.h>

#define NSP   16384
#define NPIX  (512*512)
#define NE    262144
#define CAP   64        // max entries per segment (mean 16, 12-sigma bound)

// ---------------------------------------------------------------------------
// Static scratch (no allocations allowed)
// ---------------------------------------------------------------------------
struct __align__(256) Scratch {
    __half sp [NSP * 128];    // pooled superpixel features (fp16)
    __half hb0[NSP * 128];    // layer ping (fp16)
    __half hb1[NSP * 128];    // layer pong (fp16)
    __half h4h[NSP * 128];    // H1+H2+H3 (fp16, A input of P-GEMM)
    float  h4 [NSP * 128];    // H1+H2+H3 fp32 accumulator
    float  abA[NSP * 128];    // per-node A-half (fp32)
    __half abB[NSP * 128];    // per-node B-half (fp16, gathered by segmax)
    __half wp1t[256 * 128];   // W1 folded, TRANSPOSED [n][k] fp16
    __half wp2t[256 * 128];   // W2 folded, TRANSPOSED [n][k] fp16
    __half wfoldt[144 * 128]; // folded conv*linear, TRANSPOSED [n][k] fp16
    float  biasf[16];         // bc@Wl + bl (full precision)
    float  P  [NSP * 144];    // per-superpixel tap contributions
    int cnt_pix[NSP];
    int cnt_e  [NSP];
    int pix_lst[NSP * CAP];
    int src_lst[NSP * CAP];
};
__device__ Scratch g_s;

// ---------------------------------------------------------------------------
// Small helpers
// ---------------------------------------------------------------------------
__device__ __forceinline__ float4 f4max(float4 a, float4 b) {
    return make_float4(fmaxf(a.x, b.x), fmaxf(a.y, b.y),
                       fmaxf(a.z, b.z), fmaxf(a.w, b.w));
}
__device__ __forceinline__ float4 f4add(float4 a, float4 b) {
    return make_float4(a.x + b.x, a.y + b.y, a.z + b.z, a.w + b.w);
}
__device__ __forceinline__ float4 h4tof4(uint2 u) {
    __half2 h0 = *reinterpret_cast<__half2*>(&u.x);
    __half2 h1 = *reinterpret_cast<__half2*>(&u.y);
    float2 f0 = __half22float2(h0), f1 = __half22float2(h1);
    return make_float4(f0.x, f0.y, f1.x, f1.y);
}
__device__ __forceinline__ uint2 f4toh4(float4 v) {
    __half2 p0 = __floats2half2_rn(v.x, v.y);
    __half2 p1 = __floats2half2_rn(v.z, v.w);
    uint2 u;
    u.x = *reinterpret_cast<unsigned*>(&p0);
    u.y = *reinterpret_cast<unsigned*>(&p1);
    return u;
}

// ---------------------------------------------------------------------------
// Fused prep: zero counters + transposed fp16 weights + biasf
// ---------------------------------------------------------------------------
__global__ void k_prep(int* __restrict__ cnts,
                       const float* __restrict__ W1, __half* __restrict__ Wp1t,
                       const float* __restrict__ W2, __half* __restrict__ Wp2t,
                       const float* __restrict__ Wc, const float* __restrict__ Wl,
                       const float* __restrict__ bc, const float* __restrict__ bl,
                       __half* __restrict__ wfoldt, float* __restrict__ biasf) {
    int t = blockIdx.x * blockDim.x + threadIdx.x;
    if (t < 2 * NSP) {
        cnts[t] = 0;
    } else if (t < 2 * NSP + 2 * 32768) {
        int u = t - 2 * NSP;
        const float* W = (u < 32768) ? W1 : W2;
        __half* Wp = (u < 32768) ? Wp1t : Wp2t;
        u &= 32767;
        int n = u >> 7, k = u & 127;      // [n][k] layout
        float v;
        if (n < 128) v = W[k * 128 + n] - W[(k + 128) * 128 + n];
        else         v = W[(k + 128) * 128 + (n - 128)];
        Wp[u] = __float2half_rn(v);
    } else if (t < 2 * NSP + 2 * 32768 + 144 * 128) {
        int u = t - (2 * NSP + 2 * 32768);
        int o = u & 127;                  // k index
        int ntap = u >> 7;                // 0..143: tap*16 + n
        int tap = ntap >> 4, n = ntap & 15;
        float sm = 0.f;
        for (int c = 0; c < 128; c++)
            sm += Wc[(size_t)(c * 128 + o) * 9 + tap] * Wl[c * 16 + n];
        wfoldt[u] = __float2half_rn(sm);
    } else if (t < 2 * NSP + 2 * 32768 + 144 * 128 + 16) {
        int n = t - (2 * NSP + 2 * 32768 + 144 * 128);
        float sm = bl[n];
        for (int c = 0; c < 128; c++) sm += bc[c] * Wl[c * 16 + n];
        biasf[n] = sm;
    }
}

// ---------------------------------------------------------------------------
// Direct scatter into padded CSR (counter = degree). One pass, no scan.
// ---------------------------------------------------------------------------
__global__ void k_scat_both(const int* __restrict__ seg, int* __restrict__ cpix,
                            int* __restrict__ plst, const int* __restrict__ ei,
                            int* __restrict__ ce, int* __restrict__ elst) {
    int i = blockIdx.x * blockDim.x + threadIdx.x;
    {
        int k = seg[i];
        int p = atomicAdd(&cpix[k], 1);
        if (p < CAP) plst[k * CAP + p] = i;
    }
    {
        int d = ei[NE + i];
        int p = atomicAdd(&ce[d], 1);
        if (p < CAP) elst[d * CAP + p] = ei[i];
    }
}

// ---------------------------------------------------------------------------
// Mean pooling: one warp per superpixel; fp16 output (GEMM A input)
// ---------------------------------------------------------------------------
__global__ void k_pool(const float* __restrict__ x, const int* __restrict__ cnt,
                       const int* __restrict__ lst, __half* __restrict__ sp) {
    int w = (blockIdx.x * blockDim.x + threadIdx.x) >> 5;
    if (w >= NSP) return;
    int lane = threadIdx.x & 31;
    int c = cnt[w];
    int n = c < CAP ? c : CAP;
    int base = w * CAP;
    float4 acc = make_float4(0.f, 0.f, 0.f, 0.f);
    int j = 0;
    for (; j + 4 <= n; j += 4) {
        int p0 = lst[base + j], p1 = lst[base + j + 1];
        int p2 = lst[base + j + 2], p3 = lst[base + j + 3];
        float4 v0 = ((const float4*)(x + (size_t)p0 * 128))[lane];
        float4 v1 = ((const float4*)(x + (size_t)p1 * 128))[lane];
        float4 v2 = ((const float4*)(x + (size_t)p2 * 128))[lane];
        float4 v3 = ((const float4*)(x + (size_t)p3 * 128))[lane];
        acc = f4add(acc, f4add(f4add(v0, v1), f4add(v2, v3)));
    }
    for (; j < n; j++) {
        int p = lst[base + j];
        acc = f4add(acc, ((const float4*)(x + (size_t)p * 128))[lane]);
    }
    float inv = 1.0f / fmaxf((float)c, 1.0f);
    acc.x *= inv; acc.y *= inv; acc.z *= inv; acc.w *= inv;
    ((uint2*)(sp + (size_t)w * 128))[lane] = f4toh4(acc);
}

// ---------------------------------------------------------------------------
// FP16 tensor-core GEMM, cp.async 2-stage, 8 warps (4x2), BM=128 BN=64 BK=32.
// A [M][128] fp16 row-major; Bt [N][128] fp16 (transposed: n-major).
// Smem rows stored as u32 with stride 20 (16 payload + 4 pad): conflict-free.
// mode 0: fp32 C[M,N] (stride N). mode 1: split -> CmA fp32 / CmB fp16.
// ---------------------------------------------------------------------------
#define CPA(dst, src, sz) \
    asm volatile("cp.async.cg.shared.global [%0], [%1], 16, %2;" \
                 :: "r"(dst), "l"(src), "r"(sz))

__global__ void k_gemm_tc(const __half* __restrict__ A, const __half* __restrict__ Bt,
                          float* __restrict__ Cm, __half* __restrict__ CmB,
                          int M, int N, int mode) {
    __shared__ unsigned smw[2 * 128 * 20 + 2 * 64 * 20];   // 30 KB
    int tid = threadIdx.x;
    int warp = tid >> 5, lane = tid & 31;
    int g = lane >> 2, t = lane & 3;
    int wm = warp & 3, wn = warp >> 2;
    int row0 = blockIdx.y * 128, col0 = blockIdx.x * 64;

    // A loader: 128 rows x 4 chunks(16B=8 halves) = 512; 2/thread
    int arow = tid >> 2, aq = tid & 3;          // +64 rows for it=1... (idx>>2)
    // B loader: 64 rows x 4 chunks = 256; 1/thread
    int brow = tid >> 2, bq = tid & 3;
    int bn = col0 + brow;
    int bsz = (bn < N) ? 16 : 0;
    int bnc = (bn < N) ? bn : 0;
    const __half* aSrc = A + (size_t)(row0 + arow) * 128 + aq * 8;
    const __half* bSrc = Bt + (size_t)bnc * 128 + bq * 8;

    unsigned sbase = (unsigned)__cvta_generic_to_shared(smw);
    unsigned aDst0 = sbase + (unsigned)(arow * 20 + aq * 4) * 4;
    unsigned bDst0 = sbase + (unsigned)(2 * 128 * 20 + brow * 20 + bq * 4) * 4;

    // prologue: stage 0, k-chunk 0
#pragma unroll
    for (int it = 0; it < 2; it++)
        CPA(aDst0 + it * (64 * 20 * 4), aSrc + (size_t)(it * 64) * 128, 16);
    CPA(bDst0, bSrc, bsz);
    asm volatile("cp.async.commit_group;");

    float c[2][4][4] = {};
#pragma unroll
    for (int k0i = 0; k0i < 4; k0i++) {
        if (k0i < 3) {
            int s1 = (k0i + 1) & 1;
            int k1 = (k0i + 1) * 32;
            unsigned aD = aDst0 + s1 * (128 * 20 * 4);
            unsigned bD = bDst0 + s1 * (64 * 20 * 4);
#pragma unroll
            for (int it = 0; it < 2; it++)
                CPA(aD + it * (64 * 20 * 4), aSrc + (size_t)(it * 64) * 128 + k1, 16);
            CPA(bD, bSrc + k1, bsz);
            asm volatile("cp.async.commit_group;");
            asm volatile("cp.async.wait_group 1;");
        } else {
            asm volatile("cp.async.wait_group 0;");
        }
        __syncthreads();

        const unsigned* As = smw + (k0i & 1) * (128 * 20);
        const unsigned* Bs = smw + 2 * 128 * 20 + (k0i & 1) * (64 * 20);
#pragma unroll
        for (int ks = 0; ks < 2; ks++) {          // K=16 per step
            int k8 = ks * 8;                      // u32 offset within row
            unsigned a[2][4], b[4][2];
#pragma unroll
            for (int i = 0; i < 2; i++) {
                int rm = wm * 32 + i * 16;
                a[i][0] = As[(rm + g) * 20 + k8 + t];
                a[i][1] = As[(rm + g + 8) * 20 + k8 + t];
                a[i][2] = As[(rm + g) * 20 + k8 + 4 + t];
                a[i][3] = As[(rm + g + 8) * 20 + k8 + 4 + t];
            }
#pragma unroll
            for (int j = 0; j < 4; j++) {
                int cn = wn * 32 + j * 8 + g;
                b[j][0] = Bs[cn * 20 + k8 + t];
                b[j][1] = Bs[cn * 20 + k8 + 4 + t];
            }
#pragma unroll
            for (int i = 0; i < 2; i++)
#pragma unroll
                for (int j = 0; j < 4; j++) {
                    asm volatile(
                        "mma.sync.aligned.m16n8k16.row.col.f32.f16.f16.f32 "
                        "{%0,%1,%2,%3}, {%4,%5,%6,%7}, {%8,%9}, {%0,%1,%2,%3};"
                        : "+f"(c[i][j][0]), "+f"(c[i][j][1]),
                          "+f"(c[i][j][2]), "+f"(c[i][j][3])
                        : "r"(a[i][0]), "r"(a[i][1]), "r"(a[i][2]), "r"(a[i][3]),
                          "r"(b[j][0]), "r"(b[j][1]));
                }
        }
        __syncthreads();
    }
    if (mode == 0) {
#pragma unroll
        for (int i = 0; i < 2; i++) {
            int r = row0 + wm * 32 + i * 16 + g;
#pragma unroll
            for (int j = 0; j < 4; j++) {
                int cc = col0 + wn * 32 + j * 8 + 2 * t;
                if (cc < N) {
                    *(float2*)(Cm + (size_t)r * N + cc) = make_float2(c[i][j][0], c[i][j][1]);
                    *(float2*)(Cm + (size_t)(r + 8) * N + cc) = make_float2(c[i][j][2], c[i][j][3]);
                }
            }
        }
    } else if (col0 < 128) {
#pragma unroll
        for (int i = 0; i < 2; i++) {
            int r = row0 + wm * 32 + i * 16 + g;
#pragma unroll
            for (int j = 0; j < 4; j++) {
                int cc = col0 + wn * 32 + j * 8 + 2 * t;
                *(float2*)(Cm + (size_t)r * 128 + cc) = make_float2(c[i][j][0], c[i][j][1]);
                *(float2*)(Cm + (size_t)(r + 8) * 128 + cc) = make_float2(c[i][j][2], c[i][j][3]);
            }
        }
    } else {
#pragma unroll
        for (int i = 0; i < 2; i++) {
            int r = row0 + wm * 32 + i * 16 + g;
#pragma unroll
            for (int j = 0; j < 4; j++) {
                int cc2 = (col0 - 128) + wn * 32 + j * 8 + 2 * t;
                *(__half2*)(CmB + (size_t)r * 128 + cc2) =
                    __floats2half2_rn(c[i][j][0], c[i][j][1]);
                *(__half2*)(CmB + (size_t)(r + 8) * 128 + cc2) =
                    __floats2half2_rn(c[i][j][2], c[i][j][3]);
            }
        }
    }
}

// ---------------------------------------------------------------------------
// Segmented max + relu, fp16 B gather, high MLP. hout written fp16.
// accum: 0 = h4 init, 1 = h4 +=, 2 = h4h = fp16(h4 + o) [final].
// ---------------------------------------------------------------------------
__global__ void k_segmax(const float* __restrict__ Aarr, const __half* __restrict__ Barr,
                         const float* __restrict__ bias,
                         const int* __restrict__ cnt, const int* __restrict__ lst,
                         __half* __restrict__ hout, float* __restrict__ h4,
                         __half* __restrict__ h4h, int accum) {
    int w = (blockIdx.x * blockDim.x + threadIdx.x) >> 5;
    if (w >= NSP) return;
    int lane = threadIdx.x & 31;
    int c = cnt[w];
    int n = c < CAP ? c : CAP;
    int base = w * CAP;
    int idxA = (lane < n)      ? lst[base + lane]      : 0;
    int idxB = (32 + lane < n) ? lst[base + 32 + lane] : 0;

    float4 mv = make_float4(-INFINITY, -INFINITY, -INFINITY, -INFINITY);
    int j = 0;
    for (; j + 8 <= n; j += 8) {
        uint2 v[8];
#pragma unroll
        for (int u = 0; u < 8; u++) {
            int jj = j + u;
            int s0 = __shfl_sync(~0u, jj < 32 ? idxA : idxB, jj & 31);
            v[u] = ((const uint2*)(Barr + (size_t)s0 * 128))[lane];
        }
#pragma unroll
        for (int u = 0; u < 8; u++) mv = f4max(mv, h4tof4(v[u]));
    }
    for (; j < n; j++) {
        int s0 = __shfl_sync(~0u, j < 32 ? idxA : idxB, j & 31);
        mv = f4max(mv, h4tof4(((const uint2*)(Barr + (size_t)s0 * 128))[lane]));
    }
    float4 a  = ((const float4*)(Aarr + (size_t)w * 128))[lane];
    float4 bb = ((const float4*)bias)[lane];
    float4 o = make_float4(fmaxf(0.f, a.x + bb.x + mv.x),
                           fmaxf(0.f, a.y + bb.y + mv.y),
                           fmaxf(0.f, a.z + bb.z + mv.z),
                           fmaxf(0.f, a.w + bb.w + mv.w));
    ((uint2*)(hout + (size_t)w * 128))[lane] = f4toh4(o);
    float4* hp = (float4*)(h4 + (size_t)w * 128);
    if (accum == 0)      hp[lane] = o;
    else if (accum == 1) { float4 tt = hp[lane]; hp[lane] = f4add(tt, o); }
    else {
        float4 tt = f4add(hp[lane], o);
        ((uint2*)(h4h + (size_t)w * 128))[lane] = f4toh4(tt);
    }
}

// ---------------------------------------------------------------------------
// Final fused unpool+conv+linear: 4 threads per pixel, 4 channels each.
// ---------------------------------------------------------------------------
__global__ void k_out(const int* __restrict__ seg, const float* __restrict__ P,
                      const float* __restrict__ biasf, float* __restrict__ out) {
    int gidx = blockIdx.x * blockDim.x + threadIdx.x;
    if (gidx >= NPIX * 4) return;
    int p = gidx >> 2, q = gidx & 3;
    int y = p >> 9, x = p & 511;
    float4 acc = ((const float4*)biasf)[q];
#pragma unroll
    for (int ky = 0; ky < 3; ky++) {
        int ny = y + ky - 1;
        if ((unsigned)ny >= 512u) continue;
#pragma unroll
        for (int kx = 0; kx < 3; kx++) {
            int nx = x + kx - 1;
            if ((unsigned)nx >= 512u) continue;
            int s = seg[(ny << 9) + nx];
            float4 v = ((const float4*)(P + (size_t)s * 144 + (ky * 3 + kx) * 16))[q];
            acc = f4add(acc, v);
        }
    }
    ((float4*)out)[gidx] = acc;
}

// ---------------------------------------------------------------------------
// Launch
// ---------------------------------------------------------------------------
extern "C" void kernel_launch(void* const* d_in, const int* in_sizes, int n_in,
                              void* d_out, int out_size) {
    const float* x   = (const float*)d_in[0];
    const int*   ei  = (const int*)  d_in[1];
    const int*   seg = (const int*)  d_in[2];
    int wi = (n_in >= 12) ? 4 : 3;
    const float* W1 = (const float*)d_in[wi + 0];
    const float* b1 = (const float*)d_in[wi + 1];
    const float* W2 = (const float*)d_in[wi + 2];
    const float* b2 = (const float*)d_in[wi + 3];
    const float* Wc = (const float*)d_in[wi + 4];
    const float* bc = (const float*)d_in[wi + 5];
    const float* Wl = (const float*)d_in[wi + 6];
    const float* bl = (const float*)d_in[wi + 7];
    float* out = (float*)d_out;
    (void)in_sizes; (void)out_size;

    Scratch* s = nullptr;
    cudaGetSymbolAddress((void**)&s, g_s);

    // --- fused prep: zero counters + transposed fp16 weights ---
    int prepN = 2 * NSP + 2 * 32768 + 144 * 128 + 16;
    k_prep<<<(prepN + 255) / 256, 256>>>(s->cnt_pix, W1, s->wp1t, W2, s->wp2t,
                                         Wc, Wl, bc, bl, s->wfoldt, s->biasf);

    // --- direct padded-CSR scatter ---
    k_scat_both<<<NPIX / 256, 256>>>(seg, s->cnt_pix, s->pix_lst,
                                     ei, s->cnt_e, s->src_lst);

    // --- mean pool pixels -> superpixels (fp16 output) ---
    k_pool<<<(NSP * 32 + 255) / 256, 256>>>(x, s->cnt_pix, s->pix_lst, s->sp);

    dim3 gAB(4, NSP / 128);
    int segGrid = (NSP * 32 + 255) / 256;
    // Layer 1: H1
    k_gemm_tc<<<gAB, 256>>>(s->sp, s->wp1t, s->abA, s->abB, NSP, 256, 1);
    k_segmax<<<segGrid, 256>>>(s->abA, s->abB, b1, s->cnt_e, s->src_lst,
                               s->hb0, s->h4, s->h4h, 0);
    // Layer 2: H2 (W2)
    k_gemm_tc<<<gAB, 256>>>(s->hb0, s->wp2t, s->abA, s->abB, NSP, 256, 1);
    k_segmax<<<segGrid, 256>>>(s->abA, s->abB, b2, s->cnt_e, s->src_lst,
                               s->hb1, s->h4, s->h4h, 1);
    // Layer 3: H3 (W2 again); h4h finalized fp16
    k_gemm_tc<<<gAB, 256>>>(s->hb1, s->wp2t, s->abA, s->abB, NSP, 256, 1);
    k_segmax<<<segGrid, 256>>>(s->abA, s->abB, b2, s->cnt_e, s->src_lst,
                               s->hb0, s->h4, s->h4h, 2);

    // --- P = H4 @ Wfold ---
    dim3 gP(3, NSP / 128);
    k_gemm_tc<<<gP, 256>>>(s->h4h, s->wfoldt, s->P, nullptr, NSP, 144, 0);

    // --- final fused unpool + 3x3 conv + linear ---
    k_out<<<(NPIX * 4 + 255) / 256, 256>>>(seg, s->P, s->biasf, out);
}